// round 14
// baseline (speedup 1.0000x reference)
#include <cuda_runtime.h>
#include <cuda_bf16.h>
#include <cooperative_groups.h>
#include <cstdint>
#include <math.h>

namespace cg = cooperative_groups;

// Problem constants
#define Bn   32
#define Sn   2048
#define En   512
#define Vn   32000
#define NGRP 16      // batch groups (= clusters)
#define CPG  8       // CTAs per group / cluster (column split of W_dec)
#define NCOL 64      // columns per CTA
#define NTHR 256
#define SQRT_E 22.627416997969522f
#define EPSLN 1e-6f

// ---------- static device scratch ----------
__device__ unsigned g_ctr[NGRP * 32];            // monotonic counters, 128B apart
__device__ float    g_logits[(size_t)Bn * Vn];   // 4.1 MB logits scratch

// ---------- sync / PTX helpers ----------
__device__ __forceinline__ unsigned ld_acquire_u32(const unsigned* p) {
    unsigned v;
    asm volatile("ld.acquire.gpu.global.u32 %0, [%1];" : "=r"(v) : "l"(p) : "memory");
    return v;
}
__device__ __forceinline__ void red_release_add(unsigned* p, unsigned v) {
    asm volatile("red.release.gpu.global.add.u32 [%0], %1;" :: "l"(p), "r"(v) : "memory");
}
// packed f32x2 ops (Blackwell FFMA2)
__device__ __forceinline__ unsigned long long dupf(float x) {
    unsigned long long r; asm("mov.b64 %0, {%1, %1};" : "=l"(r) : "f"(x)); return r;
}
__device__ __forceinline__ void fma2(unsigned long long& d, unsigned long long a, unsigned long long b) {
    asm("fma.rn.f32x2 %0, %1, %2, %0;" : "+l"(d) : "l"(a), "l"(b));
}
__device__ __forceinline__ unsigned long long add2(unsigned long long a, unsigned long long b) {
    unsigned long long r; asm("add.rn.f32x2 %0, %1, %2;" : "=l"(r) : "l"(a), "l"(b)); return r;
}

// ===================== Kernel 1: recurrent scan =====================
// R10 skeleton + hybrid exchange: u + stats distributed via DSMEM
// (map_shared_rank remote stores, R2's correctness-proven pattern),
// synchronization via the proven L2 counter (red.release / ld.acquire).
// Consume phase is pure LDS (~29 cyc) instead of L2 __ldcg (~450 cyc).
__global__ void __launch_bounds__(NTHR, 1) __cluster_dims__(CPG, 1, 1)
rnn_scan_kernel(const int* __restrict__ seq,
                const float* __restrict__ emb,
                const float* __restrict__ Wdec,
                const float* __restrict__ bdec,
                const float* __restrict__ gamma,
                const float* __restrict__ beta,
                float* __restrict__ outz)
{
    __shared__ __align__(16) float zs[2 * En];        // state (2 batches)
    __shared__ __align__(16) float gs[En], bs_[En], bd[En];
    __shared__ __align__(16) float red[1024];         // matvec partials (8 warps x 128)
    __shared__ __align__(16) float2 part2[4];         // per-warp (s1,s2) stats
    __shared__ __align__(16) float ustage[128];       // this CTA's u slice (2 x 64)
    __shared__ __align__(16) float uloc[2 * 2 * En];  // double-buffered assembled u (DSMEM landing)
    __shared__ __align__(16) float statl[2 * 32];     // double-buffered stats (8 CTAs x 4)

    cg::cluster_group cl = cg::this_cluster();
    const int tid  = threadIdx.x;
    const int lane = tid & 31;
    const int wid  = tid >> 5;
    const int g    = blockIdx.x >> 3;
    const unsigned c = cl.block_rank();               // rank within cluster (0..7)

    // matvec roles (R4/R10 mapping: near-broadcast z loads)
    const int jq = tid & 15;                  // quad of 4 columns within our 64
    const int h  = tid >> 4;                  // 16-way row split: rows h*32..h*32+31
    // LN / emb roles
    const int be = tid >> 7;                  // batch half
    const int j4 = (tid << 2) & (En - 1);     // column base 0..508 step 4
    const int brow = 2 * g + be;              // global batch row

    // ---- init: W slice into registers (column pairs packed for f32x2) ----
    unsigned long long Wp[64];
    {
        const float* Wbase = Wdec + (size_t)(h * 32) * En + c * NCOL + jq * 4;
        #pragma unroll
        for (int ii = 0; ii < 32; ++ii) {
            float4 wv = __ldg((const float4*)(Wbase + (size_t)ii * En));
            unsigned long long lo, hi;
            asm("mov.b64 %0, {%2, %3};\n\tmov.b64 %1, {%4, %5};"
                : "=l"(lo), "=l"(hi) : "f"(wv.x), "f"(wv.y), "f"(wv.z), "f"(wv.w));
            Wp[ii * 2 + 0] = lo;
            Wp[ii * 2 + 1] = hi;
        }
    }
    for (int n = tid; n < En; n += NTHR) { gs[n] = gamma[n]; bs_[n] = beta[n]; bd[n] = bdec[n]; }
    // z_0 = sqrt(E) * x_0
    {
        int idx = __ldg(&seq[brow * Sn + 0]);
        float4 e0 = __ldg((const float4*)&emb[(size_t)idx * En + j4]);
        *(float4*)&zs[be * En + j4] =
            make_float4(e0.x * SQRT_E, e0.y * SQRT_E, e0.z * SQRT_E, e0.w * SQRT_E);
    }
    __syncthreads();
    cl.sync();   // all CTAs initialized before any DSMEM traffic

    unsigned* ctr = &g_ctr[g * 32];

    for (int t = 0; t < Sn; ++t) {
        __syncthreads();   // B1: zs consistent for matvec

        const int buf = t & 1;

        // prefetch next embedding (hidden under matvec)
        float4 epre = make_float4(0.f, 0.f, 0.f, 0.f);
        if (t + 1 < Sn) {
            int idx = __ldg(&seq[brow * Sn + (t + 1)]);
            epre = __ldg((const float4*)&emb[(size_t)idx * En + j4]);
        }

        // ---- matvec slice (R10 exact): W in regs, near-broadcast z loads ----
        {
            unsigned long long A00 = 0ull, A01 = 0ull, A10 = 0ull, A11 = 0ull;
            const int ib = h << 5;
            #pragma unroll
            for (int q = 0; q < 8; ++q) {
                float4 za = *(const float4*)&zs[ib + (q << 2)];
                float4 zb = *(const float4*)&zs[En + ib + (q << 2)];
                unsigned long long d;
                d = dupf(za.x); fma2(A00, Wp[(q*4+0)*2+0], d); fma2(A01, Wp[(q*4+0)*2+1], d);
                d = dupf(zb.x); fma2(A10, Wp[(q*4+0)*2+0], d); fma2(A11, Wp[(q*4+0)*2+1], d);
                d = dupf(za.y); fma2(A00, Wp[(q*4+1)*2+0], d); fma2(A01, Wp[(q*4+1)*2+1], d);
                d = dupf(zb.y); fma2(A10, Wp[(q*4+1)*2+0], d); fma2(A11, Wp[(q*4+1)*2+1], d);
                d = dupf(za.z); fma2(A00, Wp[(q*4+2)*2+0], d); fma2(A01, Wp[(q*4+2)*2+1], d);
                d = dupf(zb.z); fma2(A10, Wp[(q*4+2)*2+0], d); fma2(A11, Wp[(q*4+2)*2+1], d);
                d = dupf(za.w); fma2(A00, Wp[(q*4+3)*2+0], d); fma2(A01, Wp[(q*4+3)*2+1], d);
                d = dupf(zb.w); fma2(A10, Wp[(q*4+3)*2+0], d); fma2(A11, Wp[(q*4+3)*2+1], d);
            }
            A00 = add2(A00, __shfl_down_sync(~0u, A00, 16));
            A01 = add2(A01, __shfl_down_sync(~0u, A01, 16));
            A10 = add2(A10, __shfl_down_sync(~0u, A10, 16));
            A11 = add2(A11, __shfl_down_sync(~0u, A11, 16));
            if (lane < 16) {
                unsigned long long* r = (unsigned long long*)&red[wid * 128 + jq * 8];
                r[0] = A00; r[1] = A01; r[2] = A10; r[3] = A11;
            }
        }
        __syncthreads();   // B2

        // ---- fold 8 warp-partials, u = z + mv + b_dec -> ustage + warp stats ----
        if (tid < 128) {
            const int b = tid >> 6, jl = tid & 63;
            const int q2 = jl >> 2, k = jl & 3;
            float mv = 0.f;
            #pragma unroll
            for (int w = 0; w < 8; ++w) mv += red[w * 128 + q2 * 8 + b * 4 + k];
            const int J = c * NCOL + jl;
            float u = zs[b * En + J] + mv + bd[J];
            ustage[b * 64 + jl] = u;
            float s1 = u, s2 = u * u;
            #pragma unroll
            for (int off = 16; off; off >>= 1) {
                s1 += __shfl_xor_sync(~0u, s1, off);
                s2 += __shfl_xor_sync(~0u, s2, off);
            }
            if (lane == 0) part2[wid] = make_float2(s1, s2);
        }
        __syncthreads();   // B3: ustage + part2 ready

        // ---- DSMEM distribute: warp w pushes our slice + stats to peer w ----
        {
            const unsigned w = (unsigned)wid;
            const int b = lane >> 4, q = lane & 15;
            float4 v = *(float4*)&ustage[lane * 4];   // = [b*64 + q*4]
            float4* pu = cl.map_shared_rank(
                (float4*)&uloc[buf * (2 * En) + b * En + (int)c * NCOL + q * 4], w);
            *pu = v;
            if (lane == 0) {
                float2 p0 = part2[0], p1 = part2[1], p2 = part2[2], p3 = part2[3];
                float4 st = make_float4(p0.x + p1.x, p0.y + p1.y, p2.x + p3.x, p2.y + p3.y);
                float4* ps = cl.map_shared_rank((float4*)&statl[buf * 32 + (int)c * 4], w);
                *ps = st;
            }
        }
        __syncthreads();   // B4: all remote stores by this CTA ordered before release

        // ---- release arrive (one thread) + all-warp converged poll (R10) ----
        if (tid == 0) red_release_add(ctr, 1u);
        {
            const unsigned tgt = 8u * (unsigned)(t + 1);
            while (ld_acquire_u32(ctr) < tgt) { }
        }

        // ---- consume: ALL LOCAL SMEM -> stats shuffles + LN + fused emb add ----
        {
            float mom = statl[buf * 32 + lane];       // 8 CTAs x 4 partials (LDS)
            float4 uu = *(float4*)&uloc[buf * (2 * En) + be * En + j4];
            mom += __shfl_xor_sync(~0u, mom, 4);
            mom += __shfl_xor_sync(~0u, mom, 8);
            mom += __shfl_xor_sync(~0u, mom, 16);     // lane l: total of quantity l&3
            float S1 = __shfl_sync(~0u, mom, 2 * be);
            float S2 = __shfl_sync(~0u, mom, 2 * be + 1);
            float mu = S1 * (1.f / En);
            float va = (S2 - (float)En * mu * mu) * (1.f / (En - 1));
            float rv = __fdividef(1.f, sqrtf(va) + EPSLN);

            float4 gg = *(float4*)&gs[j4];
            float4 bb = *(float4*)&bs_[j4];
            float4 zn;
            zn.x = fmaf(gg.x, (uu.x - mu) * rv, bb.x) + SQRT_E * epre.x;
            zn.y = fmaf(gg.y, (uu.y - mu) * rv, bb.y) + SQRT_E * epre.y;
            zn.z = fmaf(gg.z, (uu.z - mu) * rv, bb.z) + SQRT_E * epre.z;
            zn.w = fmaf(gg.w, (uu.w - mu) * rv, bb.w) + SQRT_E * epre.w;
            *(float4*)&zs[be * En + j4] = zn;
        }
        // loop-top barrier orders zs writes before the next matvec
    }

    // final z -> d_out (first B*E floats), rank 0 of each cluster writes
    if (c == 0) {
        *(float4*)&outz[brow * En + j4] = *(float4*)&zs[be * En + j4];
    }
    cl.sync();   // keep smem alive for any late peer DSMEM stores
}

// ===================== Kernel 2: logits = z @ W_voc + b_voc =====================
__global__ void __launch_bounds__(128)
vocab_gemm_kernel(const float* __restrict__ z,
                  const float* __restrict__ Wvoc,
                  const float* __restrict__ bvoc)
{
    extern __shared__ float zsh[];   // 32*512 floats = 64 KB
    for (int n = threadIdx.x; n < (Bn * En) / 4; n += 128)
        ((float4*)zsh)[n] = ((const float4*)z)[n];
    __syncthreads();

    const int v = blockIdx.x * 128 + threadIdx.x;
    float bias = __ldg(&bvoc[v]);
    float acc[Bn];
    #pragma unroll
    for (int b = 0; b < Bn; ++b) acc[b] = bias;

    for (int i = 0; i < En; i += 4) {
        float w0 = __ldg(&Wvoc[(size_t)(i + 0) * Vn + v]);
        float w1 = __ldg(&Wvoc[(size_t)(i + 1) * Vn + v]);
        float w2 = __ldg(&Wvoc[(size_t)(i + 2) * Vn + v]);
        float w3 = __ldg(&Wvoc[(size_t)(i + 3) * Vn + v]);
        #pragma unroll
        for (int b = 0; b < Bn; ++b) {
            float4 zz = *(const float4*)&zsh[b * En + i];
            acc[b] = fmaf(zz.x, w0, fmaf(zz.y, w1, fmaf(zz.z, w2, fmaf(zz.w, w3, acc[b]))));
        }
    }
    #pragma unroll
    for (int b = 0; b < Bn; ++b)
        g_logits[(size_t)b * Vn + v] = acc[b];
}

// ===================== Kernel 3: log_softmax + counter reset =====================
__global__ void __launch_bounds__(256)
logsoftmax_kernel(float* __restrict__ dout)
{
    __shared__ float sb[34];
    const int row = blockIdx.x;
    const int tid = threadIdx.x;
    if (row == 0 && tid < NGRP) g_ctr[tid * 32] = 0u;   // reset for next graph replay

    const float* L = &g_logits[(size_t)row * Vn];

    float m = -INFINITY;
    for (int v = tid; v < Vn; v += 256) m = fmaxf(m, __ldg(&L[v]));
    #pragma unroll
    for (int off = 16; off; off >>= 1) m = fmaxf(m, __shfl_xor_sync(~0u, m, off));
    if ((tid & 31) == 0) sb[tid >> 5] = m;
    __syncthreads();
    if (tid < 8) {
        float mm = sb[tid];
        #pragma unroll
        for (int off = 4; off; off >>= 1) mm = fmaxf(mm, __shfl_xor_sync(0xffu, mm, off));
        if (tid == 0) sb[32] = mm;
    }
    __syncthreads();
    const float M = sb[32];
    __syncthreads();

    float s = 0.f;
    for (int v = tid; v < Vn; v += 256) s += expf(__ldg(&L[v]) - M);
    #pragma unroll
    for (int off = 16; off; off >>= 1) s += __shfl_xor_sync(~0u, s, off);
    if ((tid & 31) == 0) sb[tid >> 5] = s;
    __syncthreads();
    if (tid < 8) {
        float ss = sb[tid];
        #pragma unroll
        for (int off = 4; off; off >>= 1) ss += __shfl_xor_sync(0xffu, ss, off);
        if (tid == 0) sb[33] = ss;
    }
    __syncthreads();
    const float lse = M + logf(sb[33]);

    float* Y = dout + Bn * En + (size_t)row * Vn;
    for (int v = tid; v < Vn; v += 256) Y[v] = __ldg(&L[v]) - lse;
}

// ===================== launch =====================
extern "C" void kernel_launch(void* const* d_in, const int* in_sizes, int n_in,
                              void* d_out, int out_size)
{
    // inputs: hidden_state, output_sequence, emb_out, W_dec, b_dec, gamma, beta, W_voc, b_voc
    const int*   seq   = (const int*)  d_in[1];
    const float* emb   = (const float*)d_in[2];
    const float* Wdec  = (const float*)d_in[3];
    const float* bdec  = (const float*)d_in[4];
    const float* gamma = (const float*)d_in[5];
    const float* beta  = (const float*)d_in[6];
    const float* Wvoc  = (const float*)d_in[7];
    const float* bvoc  = (const float*)d_in[8];
    float* out = (float*)d_out;

    const int smem2 = Bn * En * (int)sizeof(float);   // 64 KB
    cudaFuncSetAttribute(vocab_gemm_kernel, cudaFuncAttributeMaxDynamicSharedMemorySize, smem2);

    rnn_scan_kernel<<<NGRP * CPG, NTHR>>>(seq, emb, Wdec, bdec, gamma, beta, out);
    vocab_gemm_kernel<<<Vn / 128, 128, smem2>>>(out, Wvoc, bvoc);
    logsoftmax_kernel<<<Bn, 256>>>(out);
}

// round 15
// speedup vs baseline: 1.5002x; 1.5002x over previous
#include <cuda_runtime.h>
#include <cuda_bf16.h>
#include <cstdint>
#include <math.h>

// Problem constants
#define Bn   32
#define Sn   2048
#define En   512
#define Vn   32000
#define NGRP 16      // batch groups
#define CPG  8       // CTAs per group (column split of W_dec)
#define NCOL 64      // columns per CTA
#define NTHR 256
#define SQRT_E 22.627416997969522f
#define EPSLN 1e-6f

// ---------- static device scratch ----------
__device__ float    g_u[2 * NGRP * 2 * En];          // double-buffered u exchange
__device__ float    g_sf[2 * NGRP * 32];             // moment partials: 8 CTAs x 4 per (buf,group)
__device__ unsigned g_ctr[NGRP * 32];                 // monotonic counters, 128B apart
__device__ float    g_logits[(size_t)Bn * Vn];       // 4.1 MB logits scratch

// ---------- sync / PTX helpers ----------
__device__ __forceinline__ unsigned ld_acquire_u32(const unsigned* p) {
    unsigned v;
    asm volatile("ld.acquire.gpu.global.u32 %0, [%1];" : "=r"(v) : "l"(p) : "memory");
    return v;
}
__device__ __forceinline__ void red_release_add(unsigned* p, unsigned v) {
    asm volatile("red.release.gpu.global.add.u32 [%0], %1;" :: "l"(p), "r"(v) : "memory");
}
// packed f32x2 ops (Blackwell FFMA2)
__device__ __forceinline__ unsigned long long dupf(float x) {
    unsigned long long r; asm("mov.b64 %0, {%1, %1};" : "=l"(r) : "f"(x)); return r;
}
__device__ __forceinline__ void fma2(unsigned long long& d, unsigned long long a, unsigned long long b) {
    asm("fma.rn.f32x2 %0, %1, %2, %0;" : "+l"(d) : "l"(a), "l"(b));
}
__device__ __forceinline__ unsigned long long add2(unsigned long long a, unsigned long long b) {
    unsigned long long r; asm("add.rn.f32x2 %0, %1, %2;" : "=l"(r) : "l"(a), "l"(b)); return r;
}

// ===================== Kernel 1: recurrent scan =====================
// R10 skeleton (proven best: 4275us) with two deltas:
//  1. B3 replaced by a fold-warp-only named barrier (bar.sync 1,128):
//     tid0 releases ~200 cyc earlier; warps 4-7 go from B2 straight to the
//     poll. Single release per CTA kept (R12 showed multiple same-line
//     atomics serialize at the LTS and delay the last release).
//  2. gamma/beta/b_dec hoisted into per-thread registers (loop-invariant);
//     their smem arrays and per-step LDS deleted.
__global__ void __launch_bounds__(NTHR, 1)
rnn_scan_kernel(const int* __restrict__ seq,
                const float* __restrict__ emb,
                const float* __restrict__ Wdec,
                const float* __restrict__ bdec,
                const float* __restrict__ gamma,
                const float* __restrict__ beta,
                float* __restrict__ outz)
{
    __shared__ __align__(16) float zs[2 * En];     // state (2 batches)
    __shared__ __align__(16) float red[1024];      // matvec partials (8 warps x 128)
    __shared__ __align__(16) float2 part2[4];      // per-warp (s1,s2) stats

    const int tid  = threadIdx.x;
    const int lane = tid & 31;
    const int wid  = tid >> 5;
    const int g    = blockIdx.x >> 3;
    const int c    = blockIdx.x & 7;

    // matvec roles (R4/R10 mapping: near-broadcast z loads)
    const int jq = tid & 15;                  // quad of 4 columns within our 64
    const int h  = tid >> 4;                  // 16-way row split: rows h*32..h*32+31
    // LN / emb roles
    const int be = tid >> 7;                  // batch half
    const int j4 = (tid << 2) & (En - 1);     // column base 0..508 step 4
    const int brow = 2 * g + be;              // global batch row
    // fold-phase column (threads 0..127)
    const int Jf = c * NCOL + (tid & 63);

    // ---- init: W slice into registers (column pairs packed for f32x2) ----
    unsigned long long Wp[64];
    {
        const float* Wbase = Wdec + (size_t)(h * 32) * En + c * NCOL + jq * 4;
        #pragma unroll
        for (int ii = 0; ii < 32; ++ii) {
            float4 wv = __ldg((const float4*)(Wbase + (size_t)ii * En));
            unsigned long long lo, hi;
            asm("mov.b64 %0, {%2, %3};\n\tmov.b64 %1, {%4, %5};"
                : "=l"(lo), "=l"(hi) : "f"(wv.x), "f"(wv.y), "f"(wv.z), "f"(wv.w));
            Wp[ii * 2 + 0] = lo;
            Wp[ii * 2 + 1] = hi;
        }
    }
    // loop-invariant per-thread constants (registers, no smem)
    const float4 gg  = __ldg((const float4*)&gamma[j4]);
    const float4 bb  = __ldg((const float4*)&beta[j4]);
    const float  bdJ = (tid < 128) ? __ldg(&bdec[Jf]) : 0.f;

    // z_0 = sqrt(E) * x_0
    {
        int idx = __ldg(&seq[brow * Sn + 0]);
        float4 e0 = __ldg((const float4*)&emb[(size_t)idx * En + j4]);
        *(float4*)&zs[be * En + j4] =
            make_float4(e0.x * SQRT_E, e0.y * SQRT_E, e0.z * SQRT_E, e0.w * SQRT_E);
    }

    unsigned* ctr = &g_ctr[g * 32];

    for (int t = 0; t < Sn; ++t) {
        __syncthreads();   // B1: zs consistent for matvec

        const int buf = t & 1;
        float* gu = &g_u[((size_t)(buf * NGRP + g) * 2) * En];   // [2][512]
        float* gp = &g_sf[(size_t)(buf * NGRP + g) * 32];        // 32 floats

        // prefetch next embedding (hidden under matvec)
        float4 epre = make_float4(0.f, 0.f, 0.f, 0.f);
        if (t + 1 < Sn) {
            int idx = __ldg(&seq[brow * Sn + (t + 1)]);
            epre = __ldg((const float4*)&emb[(size_t)idx * En + j4]);
        }

        // ---- matvec slice (R10 exact): W in regs, near-broadcast z loads ----
        {
            unsigned long long A00 = 0ull, A01 = 0ull, A10 = 0ull, A11 = 0ull;
            const int ib = h << 5;
            #pragma unroll
            for (int q = 0; q < 8; ++q) {
                float4 za = *(const float4*)&zs[ib + (q << 2)];
                float4 zb = *(const float4*)&zs[En + ib + (q << 2)];
                unsigned long long d;
                d = dupf(za.x); fma2(A00, Wp[(q*4+0)*2+0], d); fma2(A01, Wp[(q*4+0)*2+1], d);
                d = dupf(zb.x); fma2(A10, Wp[(q*4+0)*2+0], d); fma2(A11, Wp[(q*4+0)*2+1], d);
                d = dupf(za.y); fma2(A00, Wp[(q*4+1)*2+0], d); fma2(A01, Wp[(q*4+1)*2+1], d);
                d = dupf(zb.y); fma2(A10, Wp[(q*4+1)*2+0], d); fma2(A11, Wp[(q*4+1)*2+1], d);
                d = dupf(za.z); fma2(A00, Wp[(q*4+2)*2+0], d); fma2(A01, Wp[(q*4+2)*2+1], d);
                d = dupf(zb.z); fma2(A10, Wp[(q*4+2)*2+0], d); fma2(A11, Wp[(q*4+2)*2+1], d);
                d = dupf(za.w); fma2(A00, Wp[(q*4+3)*2+0], d); fma2(A01, Wp[(q*4+3)*2+1], d);
                d = dupf(zb.w); fma2(A10, Wp[(q*4+3)*2+0], d); fma2(A11, Wp[(q*4+3)*2+1], d);
            }
            A00 = add2(A00, __shfl_down_sync(~0u, A00, 16));
            A01 = add2(A01, __shfl_down_sync(~0u, A01, 16));
            A10 = add2(A10, __shfl_down_sync(~0u, A10, 16));
            A11 = add2(A11, __shfl_down_sync(~0u, A11, 16));
            if (lane < 16) {
                unsigned long long* r = (unsigned long long*)&red[wid * 128 + jq * 8];
                r[0] = A00; r[1] = A01; r[2] = A10; r[3] = A11;
            }
        }
        __syncthreads();   // B2: red[] complete

        // ---- fold warps (0-3): u, gu STG, warp stats; named bar; tid0 releases ----
        if (tid < 128) {
            const int b = tid >> 6;
            const int q2 = (tid & 63) >> 2, k = tid & 3;
            float mv = 0.f;
            #pragma unroll
            for (int w = 0; w < 8; ++w) mv += red[w * 128 + q2 * 8 + b * 4 + k];
            float u = zs[b * En + Jf] + mv + bdJ;
            gu[b * En + Jf] = u;                      // coalesced 128B per warp
            float s1 = u, s2 = u * u;
            #pragma unroll
            for (int off = 16; off; off >>= 1) {
                s1 += __shfl_xor_sync(~0u, s1, off);
                s2 += __shfl_xor_sync(~0u, s2, off);
            }
            if (lane == 0) part2[wid] = make_float2(s1, s2);
            asm volatile("bar.sync 1, 128;" ::: "memory");   // fold warps only
            if (tid == 0) {
                float2 p0 = part2[0], p1 = part2[1], p2 = part2[2], p3 = part2[3];
                *(float4*)&gp[c * 4] =
                    make_float4(p0.x + p1.x, p0.y + p1.y, p2.x + p3.x, p2.y + p3.y);
                red_release_add(ctr, 1u);
            }
        }
        // warps 4-7 skip straight to the poll (safe: consume can't pass the
        // counter until our own fold warps released, which is after their
        // zs reads — so consume writes to zs can't race the fold reads).

        // ---- poll: every thread acquires the group counter (R10 exact) ----
        {
            const unsigned tgt = 8u * (unsigned)(t + 1);
            while (ld_acquire_u32(ctr) < tgt) { }
        }

        // ---- consume: gp line + own u float4, LN fused with next emb add ----
        {
            float mom = __ldcg(&gp[lane]);            // 8 CTAs x 4 partials
            float4 uu = __ldcg((const float4*)&gu[be * En + j4]);
            mom += __shfl_xor_sync(~0u, mom, 4);
            mom += __shfl_xor_sync(~0u, mom, 8);
            mom += __shfl_xor_sync(~0u, mom, 16);     // lane l: total of quantity l&3
            float S1 = __shfl_sync(~0u, mom, 2 * be);
            float S2 = __shfl_sync(~0u, mom, 2 * be + 1);
            float mu = S1 * (1.f / En);
            float va = (S2 - (float)En * mu * mu) * (1.f / (En - 1));
            float rv = __fdividef(1.f, sqrtf(va) + EPSLN);

            float4 zn;
            zn.x = fmaf(gg.x, (uu.x - mu) * rv, bb.x) + SQRT_E * epre.x;
            zn.y = fmaf(gg.y, (uu.y - mu) * rv, bb.y) + SQRT_E * epre.y;
            zn.z = fmaf(gg.z, (uu.z - mu) * rv, bb.z) + SQRT_E * epre.z;
            zn.w = fmaf(gg.w, (uu.w - mu) * rv, bb.w) + SQRT_E * epre.w;
            *(float4*)&zs[be * En + j4] = zn;
        }
        // loop-top barrier orders zs writes before the next matvec
    }

    // final z -> d_out (first B*E floats), CTA c==0 of each group writes
    if (c == 0) {
        *(float4*)&outz[brow * En + j4] = *(float4*)&zs[be * En + j4];
    }
}

// ===================== Kernel 2: logits = z @ W_voc + b_voc =====================
__global__ void __launch_bounds__(128)
vocab_gemm_kernel(const float* __restrict__ z,
                  const float* __restrict__ Wvoc,
                  const float* __restrict__ bvoc)
{
    extern __shared__ float zsh[];   // 32*512 floats = 64 KB
    for (int n = threadIdx.x; n < (Bn * En) / 4; n += 128)
        ((float4*)zsh)[n] = ((const float4*)z)[n];
    __syncthreads();

    const int v = blockIdx.x * 128 + threadIdx.x;
    float bias = __ldg(&bvoc[v]);
    float acc[Bn];
    #pragma unroll
    for (int b = 0; b < Bn; ++b) acc[b] = bias;

    for (int i = 0; i < En; i += 4) {
        float w0 = __ldg(&Wvoc[(size_t)(i + 0) * Vn + v]);
        float w1 = __ldg(&Wvoc[(size_t)(i + 1) * Vn + v]);
        float w2 = __ldg(&Wvoc[(size_t)(i + 2) * Vn + v]);
        float w3 = __ldg(&Wvoc[(size_t)(i + 3) * Vn + v]);
        #pragma unroll
        for (int b = 0; b < Bn; ++b) {
            float4 zz = *(const float4*)&zsh[b * En + i];
            acc[b] = fmaf(zz.x, w0, fmaf(zz.y, w1, fmaf(zz.z, w2, fmaf(zz.w, w3, acc[b]))));
        }
    }
    #pragma unroll
    for (int b = 0; b < Bn; ++b)
        g_logits[(size_t)b * Vn + v] = acc[b];
}

// ===================== Kernel 3: log_softmax + counter reset =====================
__global__ void __launch_bounds__(256)
logsoftmax_kernel(float* __restrict__ dout)
{
    __shared__ float sb[34];
    const int row = blockIdx.x;
    const int tid = threadIdx.x;
    if (row == 0 && tid < NGRP) g_ctr[tid * 32] = 0u;   // reset for next graph replay

    const float* L = &g_logits[(size_t)row * Vn];

    float m = -INFINITY;
    for (int v = tid; v < Vn; v += 256) m = fmaxf(m, __ldg(&L[v]));
    #pragma unroll
    for (int off = 16; off; off >>= 1) m = fmaxf(m, __shfl_xor_sync(~0u, m, off));
    if ((tid & 31) == 0) sb[tid >> 5] = m;
    __syncthreads();
    if (tid < 8) {
        float mm = sb[tid];
        #pragma unroll
        for (int off = 4; off; off >>= 1) mm = fmaxf(mm, __shfl_xor_sync(0xffu, mm, off));
        if (tid == 0) sb[32] = mm;
    }
    __syncthreads();
    const float M = sb[32];
    __syncthreads();

    float s = 0.f;
    for (int v = tid; v < Vn; v += 256) s += expf(__ldg(&L[v]) - M);
    #pragma unroll
    for (int off = 16; off; off >>= 1) s += __shfl_xor_sync(~0u, s, off);
    if ((tid & 31) == 0) sb[tid >> 5] = s;
    __syncthreads();
    if (tid < 8) {
        float ss = sb[tid];
        #pragma unroll
        for (int off = 4; off; off >>= 1) ss += __shfl_xor_sync(0xffu, ss, off);
        if (tid == 0) sb[33] = ss;
    }
    __syncthreads();
    const float lse = M + logf(sb[33]);

    float* Y = dout + Bn * En + (size_t)row * Vn;
    for (int v = tid; v < Vn; v += 256) Y[v] = __ldg(&L[v]) - lse;
}

// ===================== launch =====================
extern "C" void kernel_launch(void* const* d_in, const int* in_sizes, int n_in,
                              void* d_out, int out_size)
{
    // inputs: hidden_state, output_sequence, emb_out, W_dec, b_dec, gamma, beta, W_voc, b_voc
    const int*   seq   = (const int*)  d_in[1];
    const float* emb   = (const float*)d_in[2];
    const float* Wdec  = (const float*)d_in[3];
    const float* bdec  = (const float*)d_in[4];
    const float* gamma = (const float*)d_in[5];
    const float* beta  = (const float*)d_in[6];
    const float* Wvoc  = (const float*)d_in[7];
    const float* bvoc  = (const float*)d_in[8];
    float* out = (float*)d_out;

    const int smem2 = Bn * En * (int)sizeof(float);   // 64 KB
    cudaFuncSetAttribute(vocab_gemm_kernel, cudaFuncAttributeMaxDynamicSharedMemorySize, smem2);

    rnn_scan_kernel<<<NGRP * CPG, NTHR>>>(seq, emb, Wdec, bdec, gamma, beta, out);
    vocab_gemm_kernel<<<Vn / 128, 128, smem2>>>(out, Wvoc, bvoc);
    logsoftmax_kernel<<<Bn, 256>>>(out);
}

// round 16
// speedup vs baseline: 1.5692x; 1.0460x over previous
#include <cuda_runtime.h>
#include <cuda_bf16.h>
#include <cstdint>
#include <math.h>

// Problem constants
#define Bn   32
#define Sn   2048
#define En   512
#define Vn   32000
#define NGRP 16      // batch groups
#define CPG  8       // CTAs per group (column split of W_dec)
#define NCOL 64      // columns per CTA
#define NTHR 256
#define SQRT_E 22.627416997969522f
#define EPSLN 1e-6f

// ---------- static device scratch ----------
__device__ float    g_u[2 * NGRP * 2 * En];          // double-buffered u exchange
__device__ float    g_sf[2 * NGRP * 32];             // moment partials: 8 CTAs x 4 per (buf,group)
__device__ unsigned g_ctr[NGRP * 32];                 // monotonic counters, 128B apart
__device__ float    g_logits[(size_t)Bn * Vn];       // 4.1 MB logits scratch

// ---------- sync / PTX helpers ----------
__device__ __forceinline__ unsigned ld_acquire_u32(const unsigned* p) {
    unsigned v;
    asm volatile("ld.acquire.gpu.global.u32 %0, [%1];" : "=r"(v) : "l"(p) : "memory");
    return v;
}
__device__ __forceinline__ void red_release_add(unsigned* p, unsigned v) {
    asm volatile("red.release.gpu.global.add.u32 [%0], %1;" :: "l"(p), "r"(v) : "memory");
}
// packed f32x2 ops (Blackwell FFMA2)
__device__ __forceinline__ unsigned long long dupf(float x) {
    unsigned long long r; asm("mov.b64 %0, {%1, %1};" : "=l"(r) : "f"(x)); return r;
}
__device__ __forceinline__ void fma2(unsigned long long& d, unsigned long long a, unsigned long long b) {
    asm("fma.rn.f32x2 %0, %1, %2, %0;" : "+l"(d) : "l"(a), "l"(b));
}
__device__ __forceinline__ unsigned long long add2(unsigned long long a, unsigned long long b) {
    unsigned long long r; asm("add.rn.f32x2 %0, %1, %2;" : "=l"(r) : "l"(a), "l"(b)); return r;
}

// ===================== Kernel 1: recurrent scan =====================
// R10 skeleton verbatim (proven best: 4275us) with ONE delta: the consume
// loads (gp line + own gu float4) are issued SPECULATIVELY inside the poll
// loop, right after each ld.acquire of the counter. When the terminating
// acquire observes tgt, the same-iteration loads are ordered after it and
// see released data — hiding the ~450-cyc L2 consume round trip inside the
// final poll iteration instead of serializing it after the poll.
__global__ void __launch_bounds__(NTHR, 1)
rnn_scan_kernel(const int* __restrict__ seq,
                const float* __restrict__ emb,
                const float* __restrict__ Wdec,
                const float* __restrict__ bdec,
                const float* __restrict__ gamma,
                const float* __restrict__ beta,
                float* __restrict__ outz)
{
    __shared__ __align__(16) float zs[2 * En];     // state (2 batches)
    __shared__ __align__(16) float gs[En], bs_[En], bd[En];
    __shared__ __align__(16) float red[1024];      // matvec partials (8 warps x 128)
    __shared__ __align__(16) float2 part2[4];      // per-warp (s1,s2) stats

    const int tid  = threadIdx.x;
    const int lane = tid & 31;
    const int wid  = tid >> 5;
    const int g    = blockIdx.x >> 3;
    const int c    = blockIdx.x & 7;

    // matvec roles (R4/R10 mapping: near-broadcast z loads)
    const int jq = tid & 15;                  // quad of 4 columns within our 64
    const int h  = tid >> 4;                  // 16-way row split: rows h*32..h*32+31
    // LN / emb roles
    const int be = tid >> 7;                  // batch half
    const int j4 = (tid << 2) & (En - 1);     // column base 0..508 step 4
    const int brow = 2 * g + be;              // global batch row

    // ---- init: W slice into registers (column pairs packed for f32x2) ----
    unsigned long long Wp[64];
    {
        const float* Wbase = Wdec + (size_t)(h * 32) * En + c * NCOL + jq * 4;
        #pragma unroll
        for (int ii = 0; ii < 32; ++ii) {
            float4 wv = __ldg((const float4*)(Wbase + (size_t)ii * En));
            unsigned long long lo, hi;
            asm("mov.b64 %0, {%2, %3};\n\tmov.b64 %1, {%4, %5};"
                : "=l"(lo), "=l"(hi) : "f"(wv.x), "f"(wv.y), "f"(wv.z), "f"(wv.w));
            Wp[ii * 2 + 0] = lo;
            Wp[ii * 2 + 1] = hi;
        }
    }
    for (int n = tid; n < En; n += NTHR) { gs[n] = gamma[n]; bs_[n] = beta[n]; bd[n] = bdec[n]; }
    // z_0 = sqrt(E) * x_0
    {
        int idx = __ldg(&seq[brow * Sn + 0]);
        float4 e0 = __ldg((const float4*)&emb[(size_t)idx * En + j4]);
        *(float4*)&zs[be * En + j4] =
            make_float4(e0.x * SQRT_E, e0.y * SQRT_E, e0.z * SQRT_E, e0.w * SQRT_E);
    }

    unsigned* ctr = &g_ctr[g * 32];

    for (int t = 0; t < Sn; ++t) {
        __syncthreads();   // B1: zs consistent for matvec

        const int buf = t & 1;
        float* gu = &g_u[((size_t)(buf * NGRP + g) * 2) * En];   // [2][512]
        float* gp = &g_sf[(size_t)(buf * NGRP + g) * 32];        // 32 floats

        // prefetch next embedding (hidden under matvec)
        float4 epre = make_float4(0.f, 0.f, 0.f, 0.f);
        if (t + 1 < Sn) {
            int idx = __ldg(&seq[brow * Sn + (t + 1)]);
            epre = __ldg((const float4*)&emb[(size_t)idx * En + j4]);
        }

        // ---- matvec slice (R10 exact): W in regs, near-broadcast z loads ----
        {
            unsigned long long A00 = 0ull, A01 = 0ull, A10 = 0ull, A11 = 0ull;
            const int ib = h << 5;
            #pragma unroll
            for (int q = 0; q < 8; ++q) {
                float4 za = *(const float4*)&zs[ib + (q << 2)];
                float4 zb = *(const float4*)&zs[En + ib + (q << 2)];
                unsigned long long d;
                d = dupf(za.x); fma2(A00, Wp[(q*4+0)*2+0], d); fma2(A01, Wp[(q*4+0)*2+1], d);
                d = dupf(zb.x); fma2(A10, Wp[(q*4+0)*2+0], d); fma2(A11, Wp[(q*4+0)*2+1], d);
                d = dupf(za.y); fma2(A00, Wp[(q*4+1)*2+0], d); fma2(A01, Wp[(q*4+1)*2+1], d);
                d = dupf(zb.y); fma2(A10, Wp[(q*4+1)*2+0], d); fma2(A11, Wp[(q*4+1)*2+1], d);
                d = dupf(za.z); fma2(A00, Wp[(q*4+2)*2+0], d); fma2(A01, Wp[(q*4+2)*2+1], d);
                d = dupf(zb.z); fma2(A10, Wp[(q*4+2)*2+0], d); fma2(A11, Wp[(q*4+2)*2+1], d);
                d = dupf(za.w); fma2(A00, Wp[(q*4+3)*2+0], d); fma2(A01, Wp[(q*4+3)*2+1], d);
                d = dupf(zb.w); fma2(A10, Wp[(q*4+3)*2+0], d); fma2(A11, Wp[(q*4+3)*2+1], d);
            }
            A00 = add2(A00, __shfl_down_sync(~0u, A00, 16));
            A01 = add2(A01, __shfl_down_sync(~0u, A01, 16));
            A10 = add2(A10, __shfl_down_sync(~0u, A10, 16));
            A11 = add2(A11, __shfl_down_sync(~0u, A11, 16));
            if (lane < 16) {
                unsigned long long* r = (unsigned long long*)&red[wid * 128 + jq * 8];
                r[0] = A00; r[1] = A01; r[2] = A10; r[3] = A11;
            }
        }
        __syncthreads();   // B2

        // ---- fold 8 warp-partials, u = z + mv + b_dec, store gu + warp stats ----
        if (tid < 128) {
            const int b = tid >> 6, jl = tid & 63;
            const int q2 = jl >> 2, k = jl & 3;
            float mv = 0.f;
            #pragma unroll
            for (int w = 0; w < 8; ++w) mv += red[w * 128 + q2 * 8 + b * 4 + k];
            const int J = c * NCOL + jl;
            float u = zs[b * En + J] + mv + bd[J];
            gu[b * En + J] = u;                       // coalesced 128B per warp
            float s1 = u, s2 = u * u;
            #pragma unroll
            for (int off = 16; off; off >>= 1) {
                s1 += __shfl_xor_sync(~0u, s1, off);
                s2 += __shfl_xor_sync(~0u, s2, off);
            }
            if (lane == 0) part2[wid] = make_float2(s1, s2);
        }
        __syncthreads();   // B3: gu stores + part2 ordered before release

        // ---- publish moment partials + release arrive (one thread) ----
        if (tid == 0) {
            float2 p0 = part2[0], p1 = part2[1], p2 = part2[2], p3 = part2[3];
            *(float4*)&gp[c * 4] =
                make_float4(p0.x + p1.x, p0.y + p1.y, p2.x + p3.x, p2.y + p3.y);
            red_release_add(ctr, 1u);
        }

        // ---- poll WITH speculative consume loads (the one delta vs R10) ----
        float mom;
        float4 uu;
        {
            const unsigned tgt = 8u * (unsigned)(t + 1);
            unsigned a;
            do {
                a   = ld_acquire_u32(ctr);                       // acquire first
                mom = __ldcg(&gp[lane]);                          // ordered after acquire
                uu  = __ldcg((const float4*)&gu[be * En + j4]);   // ordered after acquire
            } while (a < tgt);
            // loop exits with mom/uu loaded AFTER the passing acquire -> valid
        }

        // ---- consume: stats shuffles + LN fused with next emb add ----
        {
            mom += __shfl_xor_sync(~0u, mom, 4);
            mom += __shfl_xor_sync(~0u, mom, 8);
            mom += __shfl_xor_sync(~0u, mom, 16);     // lane l: total of quantity l&3
            float S1 = __shfl_sync(~0u, mom, 2 * be);
            float S2 = __shfl_sync(~0u, mom, 2 * be + 1);
            float mu = S1 * (1.f / En);
            float va = (S2 - (float)En * mu * mu) * (1.f / (En - 1));
            float rv = __fdividef(1.f, sqrtf(va) + EPSLN);

            float4 gg = *(float4*)&gs[j4];
            float4 bb = *(float4*)&bs_[j4];
            float4 zn;
            zn.x = fmaf(gg.x, (uu.x - mu) * rv, bb.x) + SQRT_E * epre.x;
            zn.y = fmaf(gg.y, (uu.y - mu) * rv, bb.y) + SQRT_E * epre.y;
            zn.z = fmaf(gg.z, (uu.z - mu) * rv, bb.z) + SQRT_E * epre.z;
            zn.w = fmaf(gg.w, (uu.w - mu) * rv, bb.w) + SQRT_E * epre.w;
            *(float4*)&zs[be * En + j4] = zn;
        }
        // loop-top barrier orders zs writes before the next matvec
    }

    // final z -> d_out (first B*E floats), CTA c==0 of each group writes
    if (c == 0) {
        *(float4*)&outz[brow * En + j4] = *(float4*)&zs[be * En + j4];
    }
}

// ===================== Kernel 2: logits = z @ W_voc + b_voc =====================
__global__ void __launch_bounds__(128)
vocab_gemm_kernel(const float* __restrict__ z,
                  const float* __restrict__ Wvoc,
                  const float* __restrict__ bvoc)
{
    extern __shared__ float zsh[];   // 32*512 floats = 64 KB
    for (int n = threadIdx.x; n < (Bn * En) / 4; n += 128)
        ((float4*)zsh)[n] = ((const float4*)z)[n];
    __syncthreads();

    const int v = blockIdx.x * 128 + threadIdx.x;
    float bias = __ldg(&bvoc[v]);
    float acc[Bn];
    #pragma unroll
    for (int b = 0; b < Bn; ++b) acc[b] = bias;

    for (int i = 0; i < En; i += 4) {
        float w0 = __ldg(&Wvoc[(size_t)(i + 0) * Vn + v]);
        float w1 = __ldg(&Wvoc[(size_t)(i + 1) * Vn + v]);
        float w2 = __ldg(&Wvoc[(size_t)(i + 2) * Vn + v]);
        float w3 = __ldg(&Wvoc[(size_t)(i + 3) * Vn + v]);
        #pragma unroll
        for (int b = 0; b < Bn; ++b) {
            float4 zz = *(const float4*)&zsh[b * En + i];
            acc[b] = fmaf(zz.x, w0, fmaf(zz.y, w1, fmaf(zz.z, w2, fmaf(zz.w, w3, acc[b]))));
        }
    }
    #pragma unroll
    for (int b = 0; b < Bn; ++b)
        g_logits[(size_t)b * Vn + v] = acc[b];
}

// ===================== Kernel 3: log_softmax + counter reset =====================
__global__ void __launch_bounds__(256)
logsoftmax_kernel(float* __restrict__ dout)
{
    __shared__ float sb[34];
    const int row = blockIdx.x;
    const int tid = threadIdx.x;
    if (row == 0 && tid < NGRP) g_ctr[tid * 32] = 0u;   // reset for next graph replay

    const float* L = &g_logits[(size_t)row * Vn];

    float m = -INFINITY;
    for (int v = tid; v < Vn; v += 256) m = fmaxf(m, __ldg(&L[v]));
    #pragma unroll
    for (int off = 16; off; off >>= 1) m = fmaxf(m, __shfl_xor_sync(~0u, m, off));
    if ((tid & 31) == 0) sb[tid >> 5] = m;
    __syncthreads();
    if (tid < 8) {
        float mm = sb[tid];
        #pragma unroll
        for (int off = 4; off; off >>= 1) mm = fmaxf(mm, __shfl_xor_sync(0xffu, mm, off));
        if (tid == 0) sb[32] = mm;
    }
    __syncthreads();
    const float M = sb[32];
    __syncthreads();

    float s = 0.f;
    for (int v = tid; v < Vn; v += 256) s += expf(__ldg(&L[v]) - M);
    #pragma unroll
    for (int off = 16; off; off >>= 1) s += __shfl_xor_sync(~0u, s, off);
    if ((tid & 31) == 0) sb[tid >> 5] = s;
    __syncthreads();
    if (tid < 8) {
        float ss = sb[tid];
        #pragma unroll
        for (int off = 4; off; off >>= 1) ss += __shfl_xor_sync(0xffu, ss, off);
        if (tid == 0) sb[33] = ss;
    }
    __syncthreads();
    const float lse = M + logf(sb[33]);

    float* Y = dout + Bn * En + (size_t)row * Vn;
    for (int v = tid; v < Vn; v += 256) Y[v] = __ldg(&L[v]) - lse;
}

// ===================== launch =====================
extern "C" void kernel_launch(void* const* d_in, const int* in_sizes, int n_in,
                              void* d_out, int out_size)
{
    // inputs: hidden_state, output_sequence, emb_out, W_dec, b_dec, gamma, beta, W_voc, b_voc
    const int*   seq   = (const int*)  d_in[1];
    const float* emb   = (const float*)d_in[2];
    const float* Wdec  = (const float*)d_in[3];
    const float* bdec  = (const float*)d_in[4];
    const float* gamma = (const float*)d_in[5];
    const float* beta  = (const float*)d_in[6];
    const float* Wvoc  = (const float*)d_in[7];
    const float* bvoc  = (const float*)d_in[8];
    float* out = (float*)d_out;

    const int smem2 = Bn * En * (int)sizeof(float);   // 64 KB
    cudaFuncSetAttribute(vocab_gemm_kernel, cudaFuncAttributeMaxDynamicSharedMemorySize, smem2);

    rnn_scan_kernel<<<NGRP * CPG, NTHR>>>(seq, emb, Wdec, bdec, gamma, beta, out);
    vocab_gemm_kernel<<<Vn / 128, 128, smem2>>>(out, Wvoc, bvoc);
    logsoftmax_kernel<<<Bn, 256>>>(out);
}